// round 5
// baseline (speedup 1.0000x reference)
#include <cuda_runtime.h>
#include <cuda_bf16.h>
#include <cstdint>

#define DIM 128
#define N_RELS 8
#define MAX_NODES 50000

// Scratch (device globals — the sanctioned no-alloc mechanism)
__device__ float g_counts[N_RELS * MAX_NODES];                       // 1.6 MB
__device__ float g_agg[(size_t)N_RELS * MAX_NODES * DIM];            // 204.8 MB

// ---------------------------------------------------------------------------
// Phase 1a: per-(rel,tgt) in-degree histogram
// ---------------------------------------------------------------------------
__global__ void count_kernel(const int* __restrict__ triples, int E, int N) {
    int e = blockIdx.x * blockDim.x + threadIdx.x;
    if (e >= E) return;
    int rel = triples[3 * e + 1];
    int tgt = triples[3 * e + 2];
    atomicAdd(&g_counts[rel * N + tgt], 1.0f);
}

// Phase 1b: counts -> reciprocals (in place). Empty keys stay finite garbage
// (1/0 = inf) but are never read by scatter, so harmless.
__global__ void invert_kernel(int total) {
    int i = blockIdx.x * blockDim.x + threadIdx.x;
    if (i >= total) return;
    float c = g_counts[i];
    g_counts[i] = (c > 0.0f) ? (1.0f / c) : 0.0f;
}

// ---------------------------------------------------------------------------
// Phase 2: scatter-aggregate. One warp per edge:
//   agg[rel*N + tgt][0:128] += features[src][0:128] * inv_count
// Each lane handles 4 floats (float4 load + red.global.add.v4.f32).
// ---------------------------------------------------------------------------
__global__ void scatter_kernel(const int* __restrict__ triples,
                               const float* __restrict__ features,
                               int E, int N) {
    int gid  = blockIdx.x * blockDim.x + threadIdx.x;
    int e    = gid >> 5;
    int lane = gid & 31;
    if (e >= E) return;

    int src = triples[3 * e + 0];
    int rel = triples[3 * e + 1];
    int tgt = triples[3 * e + 2];
    int key = rel * N + tgt;

    float val = g_counts[key];   // reciprocal, uniform across warp (broadcast)

    float4 f = reinterpret_cast<const float4*>(features)[src * (DIM / 4) + lane];
    f.x *= val; f.y *= val; f.z *= val; f.w *= val;

    float* dst = &g_agg[(size_t)key * DIM + lane * 4];
    asm volatile("red.global.add.v4.f32 [%0], {%1,%2,%3,%4};"
                 :: "l"(dst), "f"(f.x), "f"(f.y), "f"(f.z), "f"(f.w)
                 : "memory");
}

// ---------------------------------------------------------------------------
// Phase 3: SGEMM  out = AGG(50000 x 1024) @ W(1024 x 128) + bias
// AGG logical row t, column (r*128 + i)  lives at  g_agg[((size_t)r*N + t)*128 + i]
// W = weights viewed as (N_RELS*128, 128) row-major (exactly its memory layout).
// Tile 128x128, K-step 32, 256 threads, 8x8 micro-tile per thread.
// ---------------------------------------------------------------------------
#define BM 128
#define BN 128
#define BK 32
#define TM 8
#define TN 8

__global__ __launch_bounds__(256, 2)
void gemm_kernel(const float* __restrict__ W,
                 const float* __restrict__ bias,
                 float* __restrict__ out, int N) {
    __shared__ float As[BK][BM];   // 16 KB (transposed: [k][m])
    __shared__ float Bs[BK][BN];   // 16 KB

    const int block_m = blockIdx.x * BM;
    const int tid = threadIdx.x;
    const int tm = (tid / 16) * TM;   // 0..120
    const int tn = (tid % 16) * TN;   // 0..120

    float acc[TM][TN];
    #pragma unroll
    for (int i = 0; i < TM; i++)
        #pragma unroll
        for (int j = 0; j < TN; j++) acc[i][j] = 0.0f;

    const int KTOT = N_RELS * DIM;          // 1024
    #pragma unroll 1
    for (int kb = 0; kb < KTOT / BK; kb++) {
        const int r   = (kb * BK) / DIM;    // relation for this K-block
        const int kk0 = (kb * BK) % DIM;    // offset within relation chunk

        // --- load A tile (128 rows x 32 cols), transposed into As[k][m] ---
        #pragma unroll
        for (int i = 0; i < 4; i++) {
            int l   = tid + i * 256;        // 0..1023
            int row = l >> 3;               // 0..127
            int c4  = (l & 7) * 4;          // 0..28
            int gm  = block_m + row;
            float4 v = make_float4(0.f, 0.f, 0.f, 0.f);
            if (gm < N)
                v = *reinterpret_cast<const float4*>(
                        &g_agg[((size_t)r * N + gm) * DIM + kk0 + c4]);
            As[c4 + 0][row] = v.x;
            As[c4 + 1][row] = v.y;
            As[c4 + 2][row] = v.z;
            As[c4 + 3][row] = v.w;
        }
        // --- load B tile (32 rows x 128 cols) straight copy ---
        #pragma unroll
        for (int i = 0; i < 4; i++) {
            int l   = tid + i * 256;
            int row = l >> 5;               // 0..31
            int c4  = (l & 31) * 4;         // 0..124
            *reinterpret_cast<float4*>(&Bs[row][c4]) =
                *reinterpret_cast<const float4*>(&W[(size_t)(kb * BK + row) * DIM + c4]);
        }
        __syncthreads();

        // --- compute ---
        #pragma unroll
        for (int kk = 0; kk < BK; kk++) {
            float4 a0 = *reinterpret_cast<const float4*>(&As[kk][tm]);
            float4 a1 = *reinterpret_cast<const float4*>(&As[kk][tm + 4]);
            float4 b0 = *reinterpret_cast<const float4*>(&Bs[kk][tn]);
            float4 b1 = *reinterpret_cast<const float4*>(&Bs[kk][tn + 4]);
            float a[TM] = {a0.x, a0.y, a0.z, a0.w, a1.x, a1.y, a1.z, a1.w};
            float b[TN] = {b0.x, b0.y, b0.z, b0.w, b1.x, b1.y, b1.z, b1.w};
            #pragma unroll
            for (int i = 0; i < TM; i++)
                #pragma unroll
                for (int j = 0; j < TN; j++)
                    acc[i][j] += a[i] * b[j];
        }
        __syncthreads();
    }

    // --- epilogue: + bias, store ---
    #pragma unroll
    for (int i = 0; i < TM; i++) {
        int gm = block_m + tm + i;
        if (gm >= N) break;
        #pragma unroll
        for (int j = 0; j < TN; j += 4) {
            float4 v;
            v.x = acc[i][j + 0] + bias[tn + j + 0];
            v.y = acc[i][j + 1] + bias[tn + j + 1];
            v.z = acc[i][j + 2] + bias[tn + j + 2];
            v.w = acc[i][j + 3] + bias[tn + j + 3];
            *reinterpret_cast<float4*>(&out[(size_t)gm * DIM + tn + j]) = v;
        }
    }
}

// ---------------------------------------------------------------------------
extern "C" void kernel_launch(void* const* d_in, const int* in_sizes, int n_in,
                              void* d_out, int out_size) {
    const int*   triples  = (const int*)d_in[0];
    const float* features = (const float*)d_in[1];
    const float* weights  = (const float*)d_in[2];
    const float* bias     = (const float*)d_in[3];
    float*       out      = (float*)d_out;

    const int E = in_sizes[0] / 3;
    const int N = in_sizes[1] / DIM;

    void* cptr; cudaGetSymbolAddress(&cptr, g_counts);
    void* aptr; cudaGetSymbolAddress(&aptr, g_agg);
    cudaMemsetAsync(cptr, 0, (size_t)N_RELS * N * sizeof(float));
    cudaMemsetAsync(aptr, 0, (size_t)N_RELS * N * DIM * sizeof(float));

    count_kernel<<<(E + 255) / 256, 256>>>(triples, E, N);
    invert_kernel<<<(N_RELS * N + 255) / 256, 256>>>(N_RELS * N);

    long long threads = (long long)E * 32;
    scatter_kernel<<<(unsigned)((threads + 255) / 256), 256>>>(triples, features, E, N);

    gemm_kernel<<<(N + BM - 1) / BM, 256>>>(weights, bias, out, N);
}

// round 11
// speedup vs baseline: 1.8617x; 1.8617x over previous
#include <cuda_runtime.h>
#include <cuda_bf16.h>
#include <cstdint>

#define DIM 128
#define N_RELS 8
#define MAX_NODES 50000
#define KTOT (N_RELS * DIM)      /* 1024 */
#define BK 32                    /* K chunk */
#define NCHUNKS (KTOT / BK)      /* 32 */
#define PITCH 40                 /* smem row pitch in bf16 elems (80B) */

// ---------------------------------------------------------------------------
// Device-global scratch (no allocation allowed in kernel_launch)
// ---------------------------------------------------------------------------
__device__ float g_counts[N_RELS * MAX_NODES];                      // 1.6 MB
__device__ float g_agg[(size_t)N_RELS * MAX_NODES * DIM];           // 204.8 MB
__device__ __nv_bfloat16 g_wT_hi[DIM * KTOT];                       // W^T hi [n][k]
__device__ __nv_bfloat16 g_wT_lo[DIM * KTOT];                       // W^T lo [n][k]

__device__ __forceinline__ uint32_t smem_u32(const void* p) {
    uint32_t a;
    asm("{ .reg .u64 t; cvta.to.shared.u64 t, %1; cvt.u32.u64 %0, t; }"
        : "=r"(a) : "l"(p));
    return a;
}
__device__ __forceinline__ uint32_t pack_bf16x2(__nv_bfloat16 a, __nv_bfloat16 b) {
    return (uint32_t)__bfloat16_as_ushort(a) |
           ((uint32_t)__bfloat16_as_ushort(b) << 16);
}

#define LDSM_X4(r0, r1, r2, r3, addr)                                          \
    asm volatile("ldmatrix.sync.aligned.m8n8.x4.shared.b16 {%0,%1,%2,%3}, [%4];" \
                 : "=r"(r0), "=r"(r1), "=r"(r2), "=r"(r3) : "r"(addr))

#define MMA_BF16(d, a, b)                                                      \
    asm volatile("mma.sync.aligned.m16n8k16.row.col.f32.bf16.bf16.f32 "        \
                 "{%0,%1,%2,%3}, {%4,%5,%6,%7}, {%8,%9}, {%0,%1,%2,%3};"       \
                 : "+f"((d)[0]), "+f"((d)[1]), "+f"((d)[2]), "+f"((d)[3])      \
                 : "r"((a)[0]), "r"((a)[1]), "r"((a)[2]), "r"((a)[3]),         \
                   "r"((b)[0]), "r"((b)[1]))

// ---------------------------------------------------------------------------
// Phase 0: split + transpose W (1024x128 fp32, [k][n]) -> wT_hi/lo [n][k] bf16
// ---------------------------------------------------------------------------
__global__ void wsplit_kernel(const float* __restrict__ W) {
    int i = blockIdx.x * blockDim.x + threadIdx.x;
    if (i >= KTOT * DIM) return;
    int k = i / DIM, n = i % DIM;
    float v = W[i];
    __nv_bfloat16 hi = __float2bfloat16(v);
    float lo = v - __bfloat162float(hi);
    g_wT_hi[n * KTOT + k] = hi;
    g_wT_lo[n * KTOT + k] = __float2bfloat16(lo);
}

// ---------------------------------------------------------------------------
// Phase 1: per-(rel,tgt) degree histogram, then invert in place
// ---------------------------------------------------------------------------
__global__ void count_kernel(const int* __restrict__ triples, int E, int N) {
    int e = blockIdx.x * blockDim.x + threadIdx.x;
    if (e >= E) return;
    int rel = triples[3 * e + 1];
    int tgt = triples[3 * e + 2];
    atomicAdd(&g_counts[rel * N + tgt], 1.0f);
}
__global__ void invert_kernel(int total) {
    int i = blockIdx.x * blockDim.x + threadIdx.x;
    if (i >= total) return;
    float c = g_counts[i];
    g_counts[i] = (c > 0.0f) ? (1.0f / c) : 0.0f;
}

// ---------------------------------------------------------------------------
// Phase 2: scatter-aggregate. One warp per edge.
// ---------------------------------------------------------------------------
__global__ void scatter_kernel(const int* __restrict__ triples,
                               const float* __restrict__ features,
                               int E, int N) {
    int gid  = blockIdx.x * blockDim.x + threadIdx.x;
    int e    = gid >> 5;
    int lane = gid & 31;
    if (e >= E) return;

    int src = triples[3 * e + 0];
    int rel = triples[3 * e + 1];
    int tgt = triples[3 * e + 2];
    int key = rel * N + tgt;

    float val = g_counts[key];

    float4 f = reinterpret_cast<const float4*>(features)[src * (DIM / 4) + lane];
    f.x *= val; f.y *= val; f.z *= val; f.w *= val;

    float* dst = &g_agg[(size_t)key * DIM + lane * 4];
    asm volatile("red.global.add.v4.f32 [%0], {%1,%2,%3,%4};"
                 :: "l"(dst), "f"(f.x), "f"(f.y), "f"(f.z), "f"(f.w)
                 : "memory");
}

// ---------------------------------------------------------------------------
// Phase 3: HMMA GEMM  out = AGG(50000 x 1024) @ W(1024 x 128) + bias
// mma.sync.m16n8k16 bf16, 3-term split: D += Ahi*Bhi + Alo*Bhi + Ahi*Blo.
// CTA: 128x128 tile; 8 warps, each 64x32 (4x4 frag grid); K in 32 chunks of 32.
// Register-prefetch pipeline hides A(DRAM)/B(L2) latency under MMA.
// ---------------------------------------------------------------------------
__global__ __launch_bounds__(256)
void gemm_mma_kernel(const float* __restrict__ bias,
                     float* __restrict__ out, int N) {
    __shared__ __align__(16) __nv_bfloat16 sAh[128 * PITCH];
    __shared__ __align__(16) __nv_bfloat16 sAl[128 * PITCH];
    __shared__ __align__(16) __nv_bfloat16 sBh[128 * PITCH];
    __shared__ __align__(16) __nv_bfloat16 sBl[128 * PITCH];

    const int tid  = threadIdx.x;
    const int lane = tid & 31;
    const int wid  = tid >> 5;
    const int warp_m = (wid & 1) * 64;     // 0 / 64
    const int warp_n = (wid >> 1) * 32;    // 0..96
    const int block_m = blockIdx.x * 128;

    // --- prefetch mappings ---
    const int a_row  = tid >> 1;           // 0..127
    const int a_half = tid & 1;            // k half (16 floats)
    const int a_gm   = block_m + a_row;
    // B: two segments per thread per buffer
    const int b_row0 = tid >> 2, b_q0 = tid & 3;
    const int b_row1 = (tid + 256) >> 2, b_q1 = tid & 3;   // (tid+256)&3 == tid&3

    float4 va[4];
    uint4  vbh[2], vbl[2];

    auto load_chunk = [&](int c) {
        const int r   = c >> 2;                    // relation
        const int kk0 = (c & 3) * BK;              // 0,32,64,96
        if (a_gm < N) {
            const float4* src = reinterpret_cast<const float4*>(
                &g_agg[((size_t)r * N + a_gm) * DIM + kk0 + a_half * 16]);
            va[0] = src[0]; va[1] = src[1]; va[2] = src[2]; va[3] = src[3];
        } else {
            va[0] = va[1] = va[2] = va[3] = make_float4(0.f, 0.f, 0.f, 0.f);
        }
        vbh[0] = *reinterpret_cast<const uint4*>(&g_wT_hi[b_row0 * KTOT + c * BK + b_q0 * 8]);
        vbh[1] = *reinterpret_cast<const uint4*>(&g_wT_hi[b_row1 * KTOT + c * BK + b_q1 * 8]);
        vbl[0] = *reinterpret_cast<const uint4*>(&g_wT_lo[b_row0 * KTOT + c * BK + b_q0 * 8]);
        vbl[1] = *reinterpret_cast<const uint4*>(&g_wT_lo[b_row1 * KTOT + c * BK + b_q1 * 8]);
    };

    auto store_chunk = [&]() {
        // A: convert 16 fp32 -> hi/lo bf16, 2x uint4 each
        uint32_t hi[8], lo[8];
        #pragma unroll
        for (int j = 0; j < 4; j++) {
            float4 v = va[j];
            __nv_bfloat16 hx = __float2bfloat16(v.x), hy = __float2bfloat16(v.y);
            __nv_bfloat16 hz = __float2bfloat16(v.z), hw = __float2bfloat16(v.w);
            hi[2*j+0] = pack_bf16x2(hx, hy);
            hi[2*j+1] = pack_bf16x2(hz, hw);
            lo[2*j+0] = pack_bf16x2(__float2bfloat16(v.x - __bfloat162float(hx)),
                                    __float2bfloat16(v.y - __bfloat162float(hy)));
            lo[2*j+1] = pack_bf16x2(__float2bfloat16(v.z - __bfloat162float(hz)),
                                    __float2bfloat16(v.w - __bfloat162float(hw)));
        }
        uint4* dAh = reinterpret_cast<uint4*>(&sAh[a_row * PITCH + a_half * 16]);
        uint4* dAl = reinterpret_cast<uint4*>(&sAl[a_row * PITCH + a_half * 16]);
        dAh[0] = make_uint4(hi[0], hi[1], hi[2], hi[3]);
        dAh[1] = make_uint4(hi[4], hi[5], hi[6], hi[7]);
        dAl[0] = make_uint4(lo[0], lo[1], lo[2], lo[3]);
        dAl[1] = make_uint4(lo[4], lo[5], lo[6], lo[7]);
        // B
        *reinterpret_cast<uint4*>(&sBh[b_row0 * PITCH + b_q0 * 8]) = vbh[0];
        *reinterpret_cast<uint4*>(&sBh[b_row1 * PITCH + b_q1 * 8]) = vbh[1];
        *reinterpret_cast<uint4*>(&sBl[b_row0 * PITCH + b_q0 * 8]) = vbl[0];
        *reinterpret_cast<uint4*>(&sBl[b_row1 * PITCH + b_q1 * 8]) = vbl[1];
    };

    // ldmatrix lane addressing (element offsets; *2 for bytes)
    const int lm_arow = (lane & 7) + ((lane >> 3) & 1) * 8;  // A: row within 16
    const int lm_akof = ((lane >> 4) & 1) * 8;               // A: k offset
    const int lm_brow = (lane & 7) + ((lane >> 4) & 1) * 8;  // B: n within 16
    const int lm_bkof = ((lane >> 3) & 1) * 8;               // B: k offset

    const uint32_t base_Ah = smem_u32(sAh), base_Al = smem_u32(sAl);
    const uint32_t base_Bh = smem_u32(sBh), base_Bl = smem_u32(sBl);

    float acc[4][4][4];
    #pragma unroll
    for (int i = 0; i < 4; i++)
        #pragma unroll
        for (int j = 0; j < 4; j++)
            #pragma unroll
            for (int q = 0; q < 4; q++) acc[i][j][q] = 0.0f;

    load_chunk(0);

    #pragma unroll 1
    for (int c = 0; c < NCHUNKS; c++) {
        store_chunk();
        __syncthreads();
        if (c + 1 < NCHUNKS) load_chunk(c + 1);   // prefetch hides under MMA

        #pragma unroll
        for (int kk = 0; kk < BK; kk += 16) {
            uint32_t ah[4][4], al[4][4], bh[4][2], bl[4][2];
            #pragma unroll
            for (int mf = 0; mf < 4; mf++) {
                uint32_t off = ((warp_m + mf * 16 + lm_arow) * PITCH +
                                kk + lm_akof) * 2;
                LDSM_X4(ah[mf][0], ah[mf][1], ah[mf][2], ah[mf][3], base_Ah + off);
                LDSM_X4(al[mf][0], al[mf][1], al[mf][2], al[mf][3], base_Al + off);
            }
            #pragma unroll
            for (int nb = 0; nb < 2; nb++) {
                uint32_t off = ((warp_n + nb * 16 + lm_brow) * PITCH +
                                kk + lm_bkof) * 2;
                uint32_t r0, r1, r2, r3;
                LDSM_X4(r0, r1, r2, r3, base_Bh + off);
                bh[2*nb][0] = r0; bh[2*nb][1] = r1;
                bh[2*nb+1][0] = r2; bh[2*nb+1][1] = r3;
                LDSM_X4(r0, r1, r2, r3, base_Bl + off);
                bl[2*nb][0] = r0; bl[2*nb][1] = r1;
                bl[2*nb+1][0] = r2; bl[2*nb+1][1] = r3;
            }
            #pragma unroll
            for (int mf = 0; mf < 4; mf++)
                #pragma unroll
                for (int nf = 0; nf < 4; nf++) {
                    MMA_BF16(acc[mf][nf], ah[mf], bh[nf]);
                    MMA_BF16(acc[mf][nf], al[mf], bh[nf]);
                    MMA_BF16(acc[mf][nf], ah[mf], bl[nf]);
                }
        }
        __syncthreads();
    }

    // --- epilogue: + bias, store float2 pairs ---
    #pragma unroll
    for (int mf = 0; mf < 4; mf++) {
        int row0 = block_m + warp_m + mf * 16 + (lane >> 2);
        #pragma unroll
        for (int nf = 0; nf < 4; nf++) {
            int col = warp_n + nf * 8 + (lane & 3) * 2;
            float b0 = bias[col], b1 = bias[col + 1];
            if (row0 < N) {
                float2 v = make_float2(acc[mf][nf][0] + b0, acc[mf][nf][1] + b1);
                *reinterpret_cast<float2*>(&out[(size_t)row0 * DIM + col]) = v;
            }
            int row1 = row0 + 8;
            if (row1 < N) {
                float2 v = make_float2(acc[mf][nf][2] + b0, acc[mf][nf][3] + b1);
                *reinterpret_cast<float2*>(&out[(size_t)row1 * DIM + col]) = v;
            }
        }
    }
}

// ---------------------------------------------------------------------------
extern "C" void kernel_launch(void* const* d_in, const int* in_sizes, int n_in,
                              void* d_out, int out_size) {
    const int*   triples  = (const int*)d_in[0];
    const float* features = (const float*)d_in[1];
    const float* weights  = (const float*)d_in[2];
    const float* bias     = (const float*)d_in[3];
    float*       out      = (float*)d_out;

    const int E = in_sizes[0] / 3;
    const int N = in_sizes[1] / DIM;

    void* cptr; cudaGetSymbolAddress(&cptr, g_counts);
    void* aptr; cudaGetSymbolAddress(&aptr, g_agg);
    cudaMemsetAsync(cptr, 0, (size_t)N_RELS * N * sizeof(float));
    cudaMemsetAsync(aptr, 0, (size_t)N_RELS * N * DIM * sizeof(float));

    wsplit_kernel<<<(KTOT * DIM + 255) / 256, 256>>>(weights);
    count_kernel<<<(E + 255) / 256, 256>>>(triples, E, N);
    invert_kernel<<<(N_RELS * N + 255) / 256, 256>>>(N_RELS * N);

    long long threads = (long long)E * 32;
    scatter_kernel<<<(unsigned)((threads + 255) / 256), 256>>>(triples, features, E, N);

    gemm_mma_kernel<<<(N + 127) / 128, 256>>>(bias, out, N);
}

// round 13
// speedup vs baseline: 3.2143x; 1.7266x over previous
#include <cuda_runtime.h>
#include <cuda_fp16.h>
#include <cstdint>

#define DIM 128
#define N_RELS 8
#define MAX_NODES 50000
#define KTOT (N_RELS * DIM)      /* 1024 */
#define BK 32                    /* K chunk */
#define NCHUNKS (KTOT / BK)      /* 32 */
#define PITCH 40                 /* smem row pitch in halves (80B) */

// ---------------------------------------------------------------------------
// Device-global scratch (no allocation allowed in kernel_launch)
// ---------------------------------------------------------------------------
__device__ float  g_counts[N_RELS * MAX_NODES];                     // 1.6 MB
__device__ __half g_agg[(size_t)N_RELS * MAX_NODES * DIM];          // 102.4 MB
__device__ __half g_wT_hi[DIM * KTOT];                              // W^T hi [n][k]
__device__ __half g_wT_lo[DIM * KTOT];                              // W^T lo [n][k]

__device__ __forceinline__ uint32_t smem_u32(const void* p) {
    uint32_t a;
    asm("{ .reg .u64 t; cvta.to.shared.u64 t, %1; cvt.u32.u64 %0, t; }"
        : "=r"(a) : "l"(p));
    return a;
}

#define LDSM_X4(r0, r1, r2, r3, addr)                                          \
    asm volatile("ldmatrix.sync.aligned.m8n8.x4.shared.b16 {%0,%1,%2,%3}, [%4];" \
                 : "=r"(r0), "=r"(r1), "=r"(r2), "=r"(r3) : "r"(addr))

#define MMA_F16(d, a, b)                                                       \
    asm volatile("mma.sync.aligned.m16n8k16.row.col.f32.f16.f16.f32 "          \
                 "{%0,%1,%2,%3}, {%4,%5,%6,%7}, {%8,%9}, {%0,%1,%2,%3};"       \
                 : "+f"((d)[0]), "+f"((d)[1]), "+f"((d)[2]), "+f"((d)[3])      \
                 : "r"((a)[0]), "r"((a)[1]), "r"((a)[2]), "r"((a)[3]),         \
                   "r"((b)[0]), "r"((b)[1]))

// ---------------------------------------------------------------------------
// Phase 0: split + transpose W (1024x128 fp32, [k][n]) -> wT_hi/lo [n][k] fp16
// ---------------------------------------------------------------------------
__global__ void wsplit_kernel(const float* __restrict__ W) {
    int i = blockIdx.x * blockDim.x + threadIdx.x;
    if (i >= KTOT * DIM) return;
    int k = i / DIM, n = i % DIM;
    float v = W[i];
    __half hi = __float2half_rn(v);
    float lo = v - __half2float(hi);
    g_wT_hi[n * KTOT + k] = hi;
    g_wT_lo[n * KTOT + k] = __float2half_rn(lo);
}

// ---------------------------------------------------------------------------
// Phase 1: per-(rel,tgt) degree histogram, then invert in place
// ---------------------------------------------------------------------------
__global__ void count_kernel(const int* __restrict__ triples, int E, int N) {
    int e = blockIdx.x * blockDim.x + threadIdx.x;
    if (e >= E) return;
    int rel = triples[3 * e + 1];
    int tgt = triples[3 * e + 2];
    atomicAdd(&g_counts[rel * N + tgt], 1.0f);
}
__global__ void invert_kernel(int total) {
    int i = blockIdx.x * blockDim.x + threadIdx.x;
    if (i >= total) return;
    float c = g_counts[i];
    g_counts[i] = (c > 0.0f) ? (1.0f / c) : 0.0f;
}

// ---------------------------------------------------------------------------
// Phase 2: scatter-aggregate. One HALF-warp (16 lanes) per edge:
//   agg[rel*N + tgt][0:128] += fp16(features[src][0:128] * inv_count)
// Each lane: 8 fp32 loads -> 4 f16x2 -> one red.global.add.noftz.v4.f16x2 (16B)
// ---------------------------------------------------------------------------
__global__ void scatter_kernel(const int* __restrict__ triples,
                               const float* __restrict__ features,
                               int E, int N) {
    int gid  = blockIdx.x * blockDim.x + threadIdx.x;
    int e    = gid >> 4;
    int lane = gid & 15;
    if (e >= E) return;

    int src = triples[3 * e + 0];
    int rel = triples[3 * e + 1];
    int tgt = triples[3 * e + 2];
    int key = rel * N + tgt;

    float val = g_counts[key];

    const float4* fsrc = reinterpret_cast<const float4*>(features) +
                         (size_t)src * (DIM / 4) + lane * 2;
    float4 f0 = fsrc[0];
    float4 f1 = fsrc[1];

    __half2 h0 = __floats2half2_rn(f0.x * val, f0.y * val);
    __half2 h1 = __floats2half2_rn(f0.z * val, f0.w * val);
    __half2 h2 = __floats2half2_rn(f1.x * val, f1.y * val);
    __half2 h3 = __floats2half2_rn(f1.z * val, f1.w * val);

    __half* dst = &g_agg[(size_t)key * DIM + lane * 8];
    asm volatile("red.global.add.noftz.v4.f16x2 [%0], {%1,%2,%3,%4};"
                 :: "l"(dst),
                    "r"(*reinterpret_cast<uint32_t*>(&h0)),
                    "r"(*reinterpret_cast<uint32_t*>(&h1)),
                    "r"(*reinterpret_cast<uint32_t*>(&h2)),
                    "r"(*reinterpret_cast<uint32_t*>(&h3))
                 : "memory");
}

// ---------------------------------------------------------------------------
// Phase 3: HMMA GEMM  out = AGG(50000 x 1024, fp16) @ W(1024 x 128) + bias
// A exact in fp16 -> 2-term split on W only: D += A*Whi + A*Wlo  (f32 accum)
// CTA: 128x128 tile; 8 warps, each 64x32 (4x4 frag grid); K in 32 chunks of 32.
// Register-prefetch pipeline hides A(DRAM)/B(L2) latency under MMA.
// ---------------------------------------------------------------------------
__global__ __launch_bounds__(256)
void gemm_mma_kernel(const float* __restrict__ bias,
                     float* __restrict__ out, int N) {
    __shared__ __align__(16) __half sA [128 * PITCH];
    __shared__ __align__(16) __half sBh[128 * PITCH];
    __shared__ __align__(16) __half sBl[128 * PITCH];

    const int tid  = threadIdx.x;
    const int lane = tid & 31;
    const int wid  = tid >> 5;
    const int warp_m = (wid & 1) * 64;     // 0 / 64
    const int warp_n = (wid >> 1) * 32;    // 0..96
    const int block_m = blockIdx.x * 128;

    // --- prefetch mappings ---
    const int a_row  = tid >> 1;           // 0..127
    const int a_half = tid & 1;            // which 16-half segment of the 32
    const int a_gm   = block_m + a_row;
    const int b_row0 = tid >> 2, b_q0 = tid & 3;      // n-rows 0..63
    const int b_row1 = 64 + (tid >> 2);               // n-rows 64..127

    uint4 va[2], vbh[2], vbl[2];

    auto load_chunk = [&](int c) {
        const int r   = c >> 2;                    // relation
        const int kk0 = (c & 3) * BK;              // 0,32,64,96
        if (a_gm < N) {
            const uint4* src = reinterpret_cast<const uint4*>(
                &g_agg[((size_t)r * N + a_gm) * DIM + kk0 + a_half * 16]);
            va[0] = src[0]; va[1] = src[1];
        } else {
            va[0] = va[1] = make_uint4(0, 0, 0, 0);
        }
        vbh[0] = *reinterpret_cast<const uint4*>(&g_wT_hi[b_row0 * KTOT + c * BK + b_q0 * 8]);
        vbh[1] = *reinterpret_cast<const uint4*>(&g_wT_hi[b_row1 * KTOT + c * BK + b_q0 * 8]);
        vbl[0] = *reinterpret_cast<const uint4*>(&g_wT_lo[b_row0 * KTOT + c * BK + b_q0 * 8]);
        vbl[1] = *reinterpret_cast<const uint4*>(&g_wT_lo[b_row1 * KTOT + c * BK + b_q0 * 8]);
    };

    auto store_chunk = [&]() {
        uint4* dA = reinterpret_cast<uint4*>(&sA[a_row * PITCH + a_half * 16]);
        dA[0] = va[0]; dA[1] = va[1];
        *reinterpret_cast<uint4*>(&sBh[b_row0 * PITCH + b_q0 * 8]) = vbh[0];
        *reinterpret_cast<uint4*>(&sBh[b_row1 * PITCH + b_q0 * 8]) = vbh[1];
        *reinterpret_cast<uint4*>(&sBl[b_row0 * PITCH + b_q0 * 8]) = vbl[0];
        *reinterpret_cast<uint4*>(&sBl[b_row1 * PITCH + b_q0 * 8]) = vbl[1];
    };

    // ldmatrix lane addressing (element offsets; *2 for bytes)
    const int lm_arow = (lane & 7) + ((lane >> 3) & 1) * 8;  // A: row within 16
    const int lm_akof = ((lane >> 4) & 1) * 8;               // A: k offset
    const int lm_brow = (lane & 7) + ((lane >> 4) & 1) * 8;  // B: n within 16
    const int lm_bkof = ((lane >> 3) & 1) * 8;               // B: k offset

    const uint32_t base_A  = smem_u32(sA);
    const uint32_t base_Bh = smem_u32(sBh), base_Bl = smem_u32(sBl);

    float acc[4][4][4];
    #pragma unroll
    for (int i = 0; i < 4; i++)
        #pragma unroll
        for (int j = 0; j < 4; j++)
            #pragma unroll
            for (int q = 0; q < 4; q++) acc[i][j][q] = 0.0f;

    load_chunk(0);

    #pragma unroll 1
    for (int c = 0; c < NCHUNKS; c++) {
        store_chunk();
        __syncthreads();
        if (c + 1 < NCHUNKS) load_chunk(c + 1);   // prefetch hides under MMA

        #pragma unroll
        for (int kk = 0; kk < BK; kk += 16) {
            uint32_t ah[4][4], bh[4][2], bl[4][2];
            #pragma unroll
            for (int mf = 0; mf < 4; mf++) {
                uint32_t off = ((warp_m + mf * 16 + lm_arow) * PITCH +
                                kk + lm_akof) * 2;
                LDSM_X4(ah[mf][0], ah[mf][1], ah[mf][2], ah[mf][3], base_A + off);
            }
            #pragma unroll
            for (int nb = 0; nb < 2; nb++) {
                uint32_t off = ((warp_n + nb * 16 + lm_brow) * PITCH +
                                kk + lm_bkof) * 2;
                uint32_t r0, r1, r2, r3;
                LDSM_X4(r0, r1, r2, r3, base_Bh + off);
                bh[2*nb][0] = r0; bh[2*nb][1] = r1;
                bh[2*nb+1][0] = r2; bh[2*nb+1][1] = r3;
                LDSM_X4(r0, r1, r2, r3, base_Bl + off);
                bl[2*nb][0] = r0; bl[2*nb][1] = r1;
                bl[2*nb+1][0] = r2; bl[2*nb+1][1] = r3;
            }
            #pragma unroll
            for (int mf = 0; mf < 4; mf++)
                #pragma unroll
                for (int nf = 0; nf < 4; nf++) {
                    MMA_F16(acc[mf][nf], ah[mf], bh[nf]);
                    MMA_F16(acc[mf][nf], ah[mf], bl[nf]);
                }
        }
        __syncthreads();
    }

    // --- epilogue: + bias, store float2 pairs ---
    #pragma unroll
    for (int mf = 0; mf < 4; mf++) {
        int row0 = block_m + warp_m + mf * 16 + (lane >> 2);
        #pragma unroll
        for (int nf = 0; nf < 4; nf++) {
            int col = warp_n + nf * 8 + (lane & 3) * 2;
            float b0 = bias[col], b1 = bias[col + 1];
            if (row0 < N) {
                float2 v = make_float2(acc[mf][nf][0] + b0, acc[mf][nf][1] + b1);
                *reinterpret_cast<float2*>(&out[(size_t)row0 * DIM + col]) = v;
            }
            int row1 = row0 + 8;
            if (row1 < N) {
                float2 v = make_float2(acc[mf][nf][2] + b0, acc[mf][nf][3] + b1);
                *reinterpret_cast<float2*>(&out[(size_t)row1 * DIM + col]) = v;
            }
        }
    }
}

// ---------------------------------------------------------------------------
extern "C" void kernel_launch(void* const* d_in, const int* in_sizes, int n_in,
                              void* d_out, int out_size) {
    const int*   triples  = (const int*)d_in[0];
    const float* features = (const float*)d_in[1];
    const float* weights  = (const float*)d_in[2];
    const float* bias     = (const float*)d_in[3];
    float*       out      = (float*)d_out;

    const int E = in_sizes[0] / 3;
    const int N = in_sizes[1] / DIM;

    void* cptr; cudaGetSymbolAddress(&cptr, g_counts);
    void* aptr; cudaGetSymbolAddress(&aptr, g_agg);
    cudaMemsetAsync(cptr, 0, (size_t)N_RELS * N * sizeof(float));
    cudaMemsetAsync(aptr, 0, (size_t)N_RELS * N * DIM * sizeof(__half));

    wsplit_kernel<<<(KTOT * DIM + 255) / 256, 256>>>(weights);
    count_kernel<<<(E + 255) / 256, 256>>>(triples, E, N);
    invert_kernel<<<(N_RELS * N + 255) / 256, 256>>>(N_RELS * N);

    long long threads = (long long)E * 16;
    scatter_kernel<<<(unsigned)((threads + 255) / 256), 256>>>(triples, features, E, N);

    gemm_mma_kernel<<<(N + 127) / 128, 256>>>(bias, out, N);
}